// round 8
// baseline (speedup 1.0000x reference)
#include <cuda_runtime.h>

// CrossLayer DCN, closed form, warp-per-2-rows:
//   t_l = <x, W_l>;  s1 = 1+t1; s2 = s1 + (s1*t2 + c2); s3 = s2 + (s2*t3 + c3)
//   out = x * s3 + (b1+b2+b3);  c2 = <b1,W2>, c3 = <b1+b2,W3>
//
// Block = 256 threads = 8 warps; W/bsum staged in smem (16KB).
// Each warp processes TWO rows simultaneously so every W/bs LDS.128 is
// amortized over both rows (L1 wavefronts per row: ~250 -> ~158).
// No barriers in the row loop. launch_bounds(256,2): 2 blocks/SM.

#define D 1024
#define DV (D / 4)
#define THREADS 256
#define WARPS 8
#define ROWS_PER_BLOCK (WARPS * 2)   // 16

__global__ __launch_bounds__(THREADS, 2)
void cross_layer_kernel(const float4* __restrict__ x4,
                        const float4* __restrict__ W4,
                        const float4* __restrict__ b4,
                        float4* __restrict__ out4)
{
    const int tid  = threadIdx.x;
    const int lane = tid & 31;
    const int wid  = tid >> 5;

    __shared__ float4 sW1[DV], sW2[DV], sW3[DV], sBs[DV];
    __shared__ float2 sRed[WARPS];

    // ---- staging: W, bsum -> smem; c2,c3 block-reduced ----
    {
        float4 w1 = __ldg(&W4[tid]);
        float4 w2 = __ldg(&W4[DV + tid]);
        float4 w3 = __ldg(&W4[2 * DV + tid]);
        float4 b1 = __ldg(&b4[tid]);
        float4 b2 = __ldg(&b4[DV + tid]);
        float4 b3 = __ldg(&b4[2 * DV + tid]);

        sW1[tid] = w1; sW2[tid] = w2; sW3[tid] = w3;
        float4 bs;
        bs.x = b1.x + b2.x + b3.x;
        bs.y = b1.y + b2.y + b3.y;
        bs.z = b1.z + b2.z + b3.z;
        bs.w = b1.w + b2.w + b3.w;
        sBs[tid] = bs;

        float p2 = b1.x * w2.x + b1.y * w2.y + b1.z * w2.z + b1.w * w2.w;
        float b12x = b1.x + b2.x, b12y = b1.y + b2.y;
        float b12z = b1.z + b2.z, b12w = b1.w + b2.w;
        float p3 = b12x * w3.x + b12y * w3.y + b12z * w3.z + b12w * w3.w;

        #pragma unroll
        for (int o = 16; o > 0; o >>= 1) {
            p2 += __shfl_xor_sync(0xFFFFFFFFu, p2, o);
            p3 += __shfl_xor_sync(0xFFFFFFFFu, p3, o);
        }
        if (lane == 0) sRed[wid] = make_float2(p2, p3);
    }
    __syncthreads();

    float c2 = 0.f, c3 = 0.f;
    #pragma unroll
    for (int i = 0; i < WARPS; i++) { c2 += sRed[i].x; c3 += sRed[i].y; }

    // ---- row loop: two rows per warp, W LDS shared across both ----
    const int rowA = blockIdx.x * ROWS_PER_BLOCK + wid * 2;
    const int baseA = rowA * DV + lane;
    const int baseB = baseA + DV;          // row A+1

    float4 xA[8], xB[8];
    #pragma unroll
    for (int i = 0; i < 8; i++) xA[i] = __ldcs(&x4[baseA + i * 32]);
    #pragma unroll
    for (int i = 0; i < 8; i++) xB[i] = __ldcs(&x4[baseB + i * 32]);

    float p1A = 0.f, p2A = 0.f, p3A = 0.f;
    float p1B = 0.f, p2B = 0.f, p3B = 0.f;
    #pragma unroll
    for (int i = 0; i < 8; i++) {
        const int idx = i * 32 + lane;
        const float4 w1 = sW1[idx];
        p1A += xA[i].x * w1.x + xA[i].y * w1.y + xA[i].z * w1.z + xA[i].w * w1.w;
        p1B += xB[i].x * w1.x + xB[i].y * w1.y + xB[i].z * w1.z + xB[i].w * w1.w;
        const float4 w2 = sW2[idx];
        p2A += xA[i].x * w2.x + xA[i].y * w2.y + xA[i].z * w2.z + xA[i].w * w2.w;
        p2B += xB[i].x * w2.x + xB[i].y * w2.y + xB[i].z * w2.z + xB[i].w * w2.w;
        const float4 w3 = sW3[idx];
        p3A += xA[i].x * w3.x + xA[i].y * w3.y + xA[i].z * w3.z + xA[i].w * w3.w;
        p3B += xB[i].x * w3.x + xB[i].y * w3.y + xB[i].z * w3.z + xB[i].w * w3.w;
    }

    // interleaved butterflies: 6 independent chains, ~130 cyc serial
    #pragma unroll
    for (int o = 16; o > 0; o >>= 1) {
        p1A += __shfl_xor_sync(0xFFFFFFFFu, p1A, o);
        p1B += __shfl_xor_sync(0xFFFFFFFFu, p1B, o);
        p2A += __shfl_xor_sync(0xFFFFFFFFu, p2A, o);
        p2B += __shfl_xor_sync(0xFFFFFFFFu, p2B, o);
        p3A += __shfl_xor_sync(0xFFFFFFFFu, p3A, o);
        p3B += __shfl_xor_sync(0xFFFFFFFFu, p3B, o);
    }

    const float s1A = 1.0f + p1A;
    const float s2A = s1A + fmaf(s1A, p2A, c2);
    const float s3A = s2A + fmaf(s2A, p3A, c3);
    const float s1B = 1.0f + p1B;
    const float s2B = s1B + fmaf(s1B, p2B, c2);
    const float s3B = s2B + fmaf(s2B, p3B, c3);

    #pragma unroll
    for (int i = 0; i < 8; i++) {
        const float4 bs = sBs[i * 32 + lane];   // shared across both rows
        float4 oA, oB;
        oA.x = fmaf(xA[i].x, s3A, bs.x);
        oA.y = fmaf(xA[i].y, s3A, bs.y);
        oA.z = fmaf(xA[i].z, s3A, bs.z);
        oA.w = fmaf(xA[i].w, s3A, bs.w);
        __stcs(&out4[baseA + i * 32], oA);
        oB.x = fmaf(xB[i].x, s3B, bs.x);
        oB.y = fmaf(xB[i].y, s3B, bs.y);
        oB.z = fmaf(xB[i].z, s3B, bs.z);
        oB.w = fmaf(xB[i].w, s3B, bs.w);
        __stcs(&out4[baseB + i * 32], oB);
    }
}

extern "C" void kernel_launch(void* const* d_in, const int* in_sizes, int n_in,
                              void* d_out, int out_size)
{
    const float4* x4 = (const float4*)d_in[0];
    const float4* W4 = (const float4*)d_in[1];
    const float4* b4 = (const float4*)d_in[2];
    float4* out4 = (float4*)d_out;

    const int B = in_sizes[0] / D;   // 16384

    cross_layer_kernel<<<B / ROWS_PER_BLOCK, THREADS>>>(x4, W4, b4, out4);
}